// round 7
// baseline (speedup 1.0000x reference)
#include <cuda_runtime.h>

// Sinkhorn: 65536 matrices of 36x36, 21 iterations of row/col log-normalization,
// temperature 0.01, output exp(log_alpha). Base-2 potential form:
//   matrix = y - U_i - V_j,  y = input * (100*log2 e)
//   row pass: U_i = lse2_j(y_ij - V_j);  col pass: V_j = lse2_i(y_ij - U_i)
//
// R7: sparse candidate lists. Terms with gap > 40 base-2 units below the max
// contribute < 2^-40 (invisible in fp32). Full exact-max passes at iters
// 0,1,2,6,10,14,18 (pipe-split exp: 8 of 36 on the FMA pipe); build passes
// (iter>=2) pack surviving indices into two uint32 regs (cap 8, dense escape).
// List passes iterate only listed terms with previous-potential shift and a
// window check + exact fallback. No register arrays -> no spills at 3 blk/SM.

#define NMAT_PER_BLOCK 8
#define THREADS 288            // 8 groups * 36 = 9 full warps
#define NDIM 36
#define STRIDE 37              // conflict-free rows & columns
#define MAT_SMEM (NDIM * STRIDE)
#define MAT_ELEMS (NDIM * NDIM)
#define SCALE 144.269504088896340736f   // 100 * log2(e)
#define NITERS 21
#define NSOFT 8
#define THRESH (-40.0f)
#define MAGIC 12582912.0f      // 1.5 * 2^23
#define WIN_LO 7.8886e-31f     // 2^-100
#define WIN_HI 1.2677e+30f     // 2^100

__device__ __forceinline__ float ex2f(float x) {
    float y; asm("ex2.approx.ftz.f32 %0, %1;" : "=f"(y) : "f"(x)); return y;
}
__device__ __forceinline__ float lg2f(float x) {
    float y; asm("lg2.approx.ftz.f32 %0, %1;" : "=f"(y) : "f"(x)); return y;
}

// FMA-pipe exp2, valid for x <= ~+38 (args here are <= 0), clamped at -126.
__device__ __forceinline__ float soft_ex2(float x) {
    x = fmaxf(x, -126.0f);
    float t = __fadd_rn(x, MAGIC);
    float n = __fadd_rn(t, -MAGIC);
    float f = x - n;                          // [-0.5, 0.5]
    float p =            1.3333558e-3f;
    p = __fmaf_rn(p, f, 9.6181291e-3f);
    p = __fmaf_rn(p, f, 5.5504109e-2f);
    p = __fmaf_rn(p, f, 2.4022651e-1f);
    p = __fmaf_rn(p, f, 6.9314718e-1f);
    p = __fmaf_rn(p, f, 1.0f);
    return __int_as_float(__float_as_int(p) + (__float_as_int(t) << 23));
}

__device__ __forceinline__ bool in_window(float s) {
    return (s > WIN_LO) && (s < WIN_HI);      // false for 0, inf, NaN, negative
}

__global__ __launch_bounds__(THREADS, 3)
void sinkhorn_kernel(const float* __restrict__ in, float* __restrict__ out)
{
    __shared__ float sy[NMAT_PER_BLOCK * MAT_SMEM];
    __shared__ __align__(16) float sU[NMAT_PER_BLOCK * NDIM];
    __shared__ __align__(16) float sV[NMAT_PER_BLOCK * NDIM];

    const int tid = threadIdx.x;
    const long long base = (long long)blockIdx.x * (NMAT_PER_BLOCK * MAT_ELEMS);

    // ---- load: coalesced float4, scatter into padded smem, fused base-2 scale
    {
        const float4* in4 = (const float4*)(in + base);
        for (int k = tid; k < (NMAT_PER_BLOCK * MAT_ELEMS) / 4; k += THREADS) {
            float4 v = in4[k];
            float vals[4] = {v.x, v.y, v.z, v.w};
            int e = k * 4;
            #pragma unroll
            for (int q = 0; q < 4; q++) {
                int idx = e + q;
                int gg  = idx / MAT_ELEMS;
                int rem = idx - gg * MAT_ELEMS;
                int r   = rem / NDIM;
                int c   = rem - r * NDIM;
                sy[gg * MAT_SMEM + r * STRIDE + c] = vals[q] * SCALE;
            }
        }
    }
    sV[tid] = 0.0f;                           // 288 == THREADS
    __syncthreads();

    const int g = tid / NDIM;
    const int l = tid - g * NDIM;

    float* U = &sU[g * NDIM];
    float* V = &sV[g * NDIM];
    const float4* V4 = (const float4*)V;
    const float4* U4 = (const float4*)U;
    const float* srow = &sy[g * MAT_SMEM + l * STRIDE];
    const float* scol = &sy[g * MAT_SMEM + l];

    float uown = 0.0f, vown = 0.0f;
    unsigned rlo = 0, rhi = 0; int rn = 36;   // row candidate list
    unsigned clo = 0, chi = 0; int cn = 36;   // col candidate list

    #pragma unroll 1
    for (int it = 0; it < NITERS; it++) {
        const bool fullit  = (it <= 2) || ((it - 2) % 4 == 0);
        const bool buildit = fullit && (it >= 2);

        // ========================= row pass =========================
        {
            float m, s;
            if (fullit) {
                // exact max
                float m0=-3e38f, m1=-3e38f, m2=-3e38f, m3=-3e38f;
                #pragma unroll
                for (int q = 0; q < 9; q++) {
                    float4 v = V4[q];
                    m0 = fmaxf(m0, srow[4*q+0] - v.x);
                    m1 = fmaxf(m1, srow[4*q+1] - v.y);
                    m2 = fmaxf(m2, srow[4*q+2] - v.z);
                    m3 = fmaxf(m3, srow[4*q+3] - v.w);
                }
                m = fmaxf(fmaxf(m0, m1), fmaxf(m2, m3));
                // sum (pipe-split) + optional build
                int cnt = 0; unsigned lo = 0, hi = 0;
                float a0 = 0.f, s0 = 0.f, s1 = 0.f, s2 = 0.f, s3 = 0.f;
                #pragma unroll
                for (int q = 0; q < 9; q++) {
                    float4 v = V4[q];
                    float x0 = (srow[4*q+0] - m) - v.x;
                    float x1 = (srow[4*q+1] - m) - v.y;
                    float x2 = (srow[4*q+2] - m) - v.z;
                    float x3 = (srow[4*q+3] - m) - v.w;
                    if (q < NSOFT/4) { a0 += soft_ex2(x0); s1 += soft_ex2(x1); }
                    else             { s0 += ex2f(x0);     s1 += ex2f(x1); }
                    s2 += ex2f(x2);
                    s3 += ex2f(x3);
                    if (buildit) {
                        float xs[4] = {x0, x1, x2, x3};
                        #pragma unroll
                        for (int u = 0; u < 4; u++) {
                            if (xs[u] > THRESH) {
                                if (cnt < 8) {
                                    unsigned enc = (unsigned)(4*q+u) << ((cnt & 3) * 8);
                                    if (cnt < 4) lo |= enc; else hi |= enc;
                                }
                                cnt++;
                            }
                        }
                    }
                }
                s = ((a0 + s0) + s1) + (s2 + s3);
                if (buildit) { rlo = lo; rhi = hi; rn = (cnt > 8) ? 36 : cnt; }
            } else {
                m = uown;
                s = 0.f;
                if (rn == 36) {
                    #pragma unroll
                    for (int q = 0; q < 9; q++) {
                        float4 v = V4[q];
                        s += ex2f((srow[4*q+0] - m) - v.x);
                        s += ex2f((srow[4*q+1] - m) - v.y);
                        s += ex2f((srow[4*q+2] - m) - v.z);
                        s += ex2f((srow[4*q+3] - m) - v.w);
                    }
                } else {
                    #pragma unroll 1
                    for (int k = 0; k < rn; k++) {
                        unsigned w = (k < 4) ? rlo : rhi;
                        int j = (w >> ((k & 3) * 8)) & 0xFF;
                        s += ex2f((srow[j] - m) - V[j]);
                    }
                }
                if (!in_window(s)) {   // rare: exact recompute
                    m = -3.0e38f;
                    #pragma unroll
                    for (int j = 0; j < NDIM; j++) m = fmaxf(m, srow[j] - V[j]);
                    s = 0.f;
                    #pragma unroll
                    for (int j = 0; j < NDIM; j++) s += ex2f((srow[j] - m) - V[j]);
                }
            }
            uown = m + lg2f(s);
            U[l] = uown;
        }
        __syncthreads();

        // ========================= col pass =========================
        {
            float m, s;
            if (fullit) {
                float m0=-3e38f, m1=-3e38f, m2=-3e38f, m3=-3e38f;
                #pragma unroll
                for (int q = 0; q < 9; q++) {
                    float4 u = U4[q];
                    m0 = fmaxf(m0, scol[(4*q+0)*STRIDE] - u.x);
                    m1 = fmaxf(m1, scol[(4*q+1)*STRIDE] - u.y);
                    m2 = fmaxf(m2, scol[(4*q+2)*STRIDE] - u.z);
                    m3 = fmaxf(m3, scol[(4*q+3)*STRIDE] - u.w);
                }
                m = fmaxf(fmaxf(m0, m1), fmaxf(m2, m3));
                int cnt = 0; unsigned lo = 0, hi = 0;
                float a0 = 0.f, s0 = 0.f, s1 = 0.f, s2 = 0.f, s3 = 0.f;
                #pragma unroll
                for (int q = 0; q < 9; q++) {
                    float4 u = U4[q];
                    float x0 = (scol[(4*q+0)*STRIDE] - m) - u.x;
                    float x1 = (scol[(4*q+1)*STRIDE] - m) - u.y;
                    float x2 = (scol[(4*q+2)*STRIDE] - m) - u.z;
                    float x3 = (scol[(4*q+3)*STRIDE] - m) - u.w;
                    if (q < NSOFT/4) { a0 += soft_ex2(x0); s1 += soft_ex2(x1); }
                    else             { s0 += ex2f(x0);     s1 += ex2f(x1); }
                    s2 += ex2f(x2);
                    s3 += ex2f(x3);
                    if (buildit) {
                        float xs[4] = {x0, x1, x2, x3};
                        #pragma unroll
                        for (int u2 = 0; u2 < 4; u2++) {
                            if (xs[u2] > THRESH) {
                                if (cnt < 8) {
                                    unsigned enc = (unsigned)(4*q+u2) << ((cnt & 3) * 8);
                                    if (cnt < 4) lo |= enc; else hi |= enc;
                                }
                                cnt++;
                            }
                        }
                    }
                }
                s = ((a0 + s0) + s1) + (s2 + s3);
                if (buildit) { clo = lo; chi = hi; cn = (cnt > 8) ? 36 : cnt; }
            } else {
                m = vown;
                s = 0.f;
                if (cn == 36) {
                    #pragma unroll
                    for (int q = 0; q < 9; q++) {
                        float4 u = U4[q];
                        s += ex2f((scol[(4*q+0)*STRIDE] - m) - u.x);
                        s += ex2f((scol[(4*q+1)*STRIDE] - m) - u.y);
                        s += ex2f((scol[(4*q+2)*STRIDE] - m) - u.z);
                        s += ex2f((scol[(4*q+3)*STRIDE] - m) - u.w);
                    }
                } else {
                    #pragma unroll 1
                    for (int k = 0; k < cn; k++) {
                        unsigned w = (k < 4) ? clo : chi;
                        int i = (w >> ((k & 3) * 8)) & 0xFF;
                        s += ex2f((scol[i * STRIDE] - m) - U[i]);
                    }
                }
                if (!in_window(s)) {
                    m = -3.0e38f;
                    #pragma unroll
                    for (int i = 0; i < NDIM; i++) m = fmaxf(m, scol[i*STRIDE] - U[i]);
                    s = 0.f;
                    #pragma unroll
                    for (int i = 0; i < NDIM; i++) s += ex2f((scol[i*STRIDE] - m) - U[i]);
                }
            }
            vown = m + lg2f(s);
            V[l] = vown;
        }
        __syncthreads();
    }

    // ---- output: overwrite sy rows with 2^(y - U - V), then float4 store
    {
        // read row into temporaries via smem (avoid aliasing issue: compute then write)
        float u = uown;
        float* od = &sy[g * MAT_SMEM + l * STRIDE];
        #pragma unroll
        for (int j = 0; j < NDIM; j += 4) {
            float4 v = V4[j/4];
            float r0 = ex2f((od[j]   - u) - v.x);
            float r1 = ex2f((od[j+1] - u) - v.y);
            float r2 = ex2f((od[j+2] - u) - v.z);
            float r3 = ex2f((od[j+3] - u) - v.w);
            od[j] = r0; od[j+1] = r1; od[j+2] = r2; od[j+3] = r3;
        }
    }
    __syncthreads();
    {
        float4* out4 = (float4*)(out + base);
        for (int k = tid; k < (NMAT_PER_BLOCK * MAT_ELEMS) / 4; k += THREADS) {
            int e = k * 4;
            float r[4];
            #pragma unroll
            for (int q = 0; q < 4; q++) {
                int idx = e + q;
                int gg  = idx / MAT_ELEMS;
                int rem = idx - gg * MAT_ELEMS;
                int rr  = rem / NDIM;
                int cc  = rem - rr * NDIM;
                r[q] = sy[gg * MAT_SMEM + rr * STRIDE + cc];
            }
            out4[k] = make_float4(r[0], r[1], r[2], r[3]);
        }
    }
}

extern "C" void kernel_launch(void* const* d_in, const int* in_sizes, int n_in,
                              void* d_out, int out_size) {
    const float* in = (const float*)d_in[0];
    float* out = (float*)d_out;
    int num_mats = in_sizes[0] / MAT_ELEMS;          // 65536
    int grid = num_mats / NMAT_PER_BLOCK;            // 8192
    sinkhorn_kernel<<<grid, THREADS>>>(in, out);
}

// round 8
// speedup vs baseline: 1.2116x; 1.2116x over previous
#include <cuda_runtime.h>

// Sinkhorn: 65536 matrices of 36x36, 21 iterations of row/col log-normalization,
// temperature 0.01, output exp(log_alpha).
//
// Potential form in base-2 domain: matrix is always  y - U_i - V_j, with
// y = input * (100*log2(e)).
//   U_i = lse2_j(y_ij - V_j)   (row pass, axis=2)
//   V_j = lse2_i(y_ij - U_i)   (col pass, axis=1)
// start V=0; after 21 (row,col) pairs, out = 2^(y - U - V).
//
// R8 = R3 skeleton (dense, branch-free, exact max each pass, t[36] register
// array, 2 blocks/SM) + ONE change: 8 of 36 exps per pass are computed by an
// FMA-pipe polynomial exp2 (soft_ex2), cutting the binding MUFU pipe from
// 37 to 29 ops/pass. Args to soft_ex2 are always <= 0 (post max-subtract),
// clamped at -126: branch-free, no fallback needed.

#define NMAT_PER_BLOCK 8
#define THREADS 288            // 8 groups * 36 = 9 full warps
#define NDIM 36
#define STRIDE 37              // 37 mod 32 = 5 -> conflict-free rows & cols
#define MAT_SMEM (NDIM * STRIDE)
#define MAT_ELEMS (NDIM * NDIM)
#define SCALE 144.269504088896340736f   // 100 * log2(e)
#define NITERS 21
#define NSOFT 8                // exps routed to the FMA pipe per pass
#define MAGIC 12582912.0f      // 1.5 * 2^23

__device__ __forceinline__ float ex2f(float x) {
    float y; asm("ex2.approx.ftz.f32 %0, %1;" : "=f"(y) : "f"(x)); return y;
}
__device__ __forceinline__ float lg2f(float x) {
    float y; asm("lg2.approx.ftz.f32 %0, %1;" : "=f"(y) : "f"(x)); return y;
}

// FMA-pipe exp2 for x <= 0 (clamped at -126 -> result flushes toward 0).
// rint via magic-number add, degree-5 poly on [-0.5, 0.5], exponent splice
// via integer add (low 9 bits of bits(MAGIC) are zero, so (bits(t)<<23) ==
// n<<23 exactly mod 2^32). Max rel err ~2.4e-6.
__device__ __forceinline__ float soft_ex2(float x) {
    x = fmaxf(x, -126.0f);
    float t = __fadd_rn(x, MAGIC);
    float n = __fadd_rn(t, -MAGIC);
    float f = x - n;                          // [-0.5, 0.5]
    float p =            1.3333558e-3f;
    p = __fmaf_rn(p, f, 9.6181291e-3f);
    p = __fmaf_rn(p, f, 5.5504109e-2f);
    p = __fmaf_rn(p, f, 2.4022651e-1f);
    p = __fmaf_rn(p, f, 6.9314718e-1f);
    p = __fmaf_rn(p, f, 1.0f);
    return __int_as_float(__float_as_int(p) + (__float_as_int(t) << 23));
}

__global__ __launch_bounds__(THREADS, 2)
void sinkhorn_kernel(const float* __restrict__ in, float* __restrict__ out)
{
    __shared__ float sy[NMAT_PER_BLOCK * MAT_SMEM];   // padded matrices (base-2 scaled)
    __shared__ float sU[NMAT_PER_BLOCK * NDIM];
    __shared__ float sV[NMAT_PER_BLOCK * NDIM];

    const int tid = threadIdx.x;
    const long long base = (long long)blockIdx.x * (NMAT_PER_BLOCK * MAT_ELEMS);

    // ---- load: coalesced float4 from global, scatter into padded smem, fused scale
    {
        const float4* in4 = (const float4*)(in + base);
        for (int k = tid; k < (NMAT_PER_BLOCK * MAT_ELEMS) / 4; k += THREADS) {
            float4 v = in4[k];
            float vals[4] = {v.x, v.y, v.z, v.w};
            int e = k * 4;
            #pragma unroll
            for (int q = 0; q < 4; q++) {
                int idx = e + q;
                int g   = idx / MAT_ELEMS;
                int rem = idx - g * MAT_ELEMS;
                int r   = rem / NDIM;
                int c   = rem - r * NDIM;
                sy[g * MAT_SMEM + r * STRIDE + c] = vals[q] * SCALE;
            }
        }
    }
    sV[tid] = 0.0f;                       // 288 == THREADS
    __syncthreads();

    const int g = tid / NDIM;          // which matrix in this block
    const int l = tid - g * NDIM;      // row index (row pass) / col index (col pass)

    float* U = &sU[g * NDIM];
    float* V = &sV[g * NDIM];

    // cache my row in registers
    float yreg[NDIM];
    {
        const float* my = &sy[g * MAT_SMEM + l * STRIDE];
        #pragma unroll
        for (int j = 0; j < NDIM; j++) yreg[j] = my[j];
    }

    const float* ycol = &sy[g * MAT_SMEM + l];   // column l, stride 37

    #pragma unroll 1
    for (int it = 0; it < NITERS; it++) {
        // ---- row pass: U[l] = m + log2(sum_j 2^(yreg[j] - V[j] - m))
        {
            float t[NDIM];
            float m0 = -1e30f, m1 = -1e30f, m2 = -1e30f, m3 = -1e30f;
            #pragma unroll
            for (int j = 0; j < NDIM; j += 4) {
                t[j]   = yreg[j]   - V[j];
                t[j+1] = yreg[j+1] - V[j+1];
                t[j+2] = yreg[j+2] - V[j+2];
                t[j+3] = yreg[j+3] - V[j+3];
                m0 = fmaxf(m0, t[j]);   m1 = fmaxf(m1, t[j+1]);
                m2 = fmaxf(m2, t[j+2]); m3 = fmaxf(m3, t[j+3]);
            }
            float m = fmaxf(fmaxf(m0, m1), fmaxf(m2, m3));
            float a0 = 0.f, a1 = 0.f;                    // FMA-pipe accumulators
            #pragma unroll
            for (int j = 0; j < NSOFT; j += 2) {
                a0 += soft_ex2(t[j]   - m);
                a1 += soft_ex2(t[j+1] - m);
            }
            float s0 = 0.f, s1 = 0.f, s2 = 0.f, s3 = 0.f; // MUFU accumulators
            #pragma unroll
            for (int j = NSOFT; j < NDIM; j += 4) {
                s0 += ex2f(t[j]   - m);
                s1 += ex2f(t[j+1] - m);
                s2 += ex2f(t[j+2] - m);
                s3 += ex2f(t[j+3] - m);
            }
            U[l] = m + lg2f(((a0 + a1) + (s0 + s1)) + (s2 + s3));
        }
        __syncthreads();

        // ---- col pass: V[l] = m + log2(sum_i 2^(y[i][l] - U[i] - m))
        {
            float t[NDIM];
            float m0 = -1e30f, m1 = -1e30f, m2 = -1e30f, m3 = -1e30f;
            #pragma unroll
            for (int i = 0; i < NDIM; i += 4) {
                t[i]   = ycol[(i)   * STRIDE] - U[i];
                t[i+1] = ycol[(i+1) * STRIDE] - U[i+1];
                t[i+2] = ycol[(i+2) * STRIDE] - U[i+2];
                t[i+3] = ycol[(i+3) * STRIDE] - U[i+3];
                m0 = fmaxf(m0, t[i]);   m1 = fmaxf(m1, t[i+1]);
                m2 = fmaxf(m2, t[i+2]); m3 = fmaxf(m3, t[i+3]);
            }
            float m = fmaxf(fmaxf(m0, m1), fmaxf(m2, m3));
            float a0 = 0.f, a1 = 0.f;
            #pragma unroll
            for (int i = 0; i < NSOFT; i += 2) {
                a0 += soft_ex2(t[i]   - m);
                a1 += soft_ex2(t[i+1] - m);
            }
            float s0 = 0.f, s1 = 0.f, s2 = 0.f, s3 = 0.f;
            #pragma unroll
            for (int i = NSOFT; i < NDIM; i += 4) {
                s0 += ex2f(t[i]   - m);
                s1 += ex2f(t[i+1] - m);
                s2 += ex2f(t[i+2] - m);
                s3 += ex2f(t[i+3] - m);
            }
            V[l] = m + lg2f(((a0 + a1) + (s0 + s1)) + (s2 + s3));
        }
        __syncthreads();
    }

    // ---- output: overwrite sy with 2^(y - U - V), split across both pipes
    {
        const float u = U[l];
        float* od = &sy[g * MAT_SMEM + l * STRIDE];
        #pragma unroll
        for (int j = 0; j < NSOFT; j++) {
            od[j] = soft_ex2((yreg[j] - u) - V[j]);
        }
        #pragma unroll
        for (int j = NSOFT; j < NDIM; j++) {
            od[j] = ex2f((yreg[j] - u) - V[j]);
        }
    }
    __syncthreads();
    {
        float4* out4 = (float4*)(out + base);
        for (int k = tid; k < (NMAT_PER_BLOCK * MAT_ELEMS) / 4; k += THREADS) {
            int e = k * 4;
            float r[4];
            #pragma unroll
            for (int q = 0; q < 4; q++) {
                int idx = e + q;
                int gg  = idx / MAT_ELEMS;
                int rem = idx - gg * MAT_ELEMS;
                int rr  = rem / NDIM;
                int cc  = rem - rr * NDIM;
                r[q] = sy[gg * MAT_SMEM + rr * STRIDE + cc];
            }
            out4[k] = make_float4(r[0], r[1], r[2], r[3]);
        }
    }
}

extern "C" void kernel_launch(void* const* d_in, const int* in_sizes, int n_in,
                              void* d_out, int out_size) {
    const float* in = (const float*)d_in[0];
    float* out = (float*)d_out;
    int num_mats = in_sizes[0] / MAT_ELEMS;          // 65536
    int grid = num_mats / NMAT_PER_BLOCK;            // 8192
    sinkhorn_kernel<<<grid, THREADS>>>(in, out);
}

// round 9
// speedup vs baseline: 1.4886x; 1.2286x over previous
#include <cuda_runtime.h>

// Sinkhorn: 65536 matrices of 36x36, 21 iterations of row/col log-normalization,
// temperature 0.01, output exp(log_alpha).
//
// Base-2 potential form: matrix = y - U_i - V_j, y = input * (100*log2 e).
//   row pass: U_i = lse2_j(y_ij - V_j);  col pass: V_j = lse2_i(y_ij - U_i)
// start V=0; after 21 (row,col) pairs, out = 2^(y - U - V).
//
// R9 = R3 structure (dense, branch-free, exact max every pass, pure MUFU) with
// the register footprint cut to fit 3 blocks/SM WITHOUT spills: no persistent
// yreg[36]; each pass loads its operand vector from smem into one short-lived
// t[36] (row: contiguous scalar LDS; col: stride-37 conflict-free). V/U are
// read as float4 broadcasts (uniform across each 36-thread group -> ~free).
// 27 warps/SM hide the barrier drain + MUFU latency that capped R3 at ~76%
// of its MUFU bound.

#define NMAT_PER_BLOCK 8
#define THREADS 288            // 8 groups * 36 = 9 full warps
#define NDIM 36
#define STRIDE 37              // 37 mod 32 = 5 -> conflict-free rows & cols
#define MAT_SMEM (NDIM * STRIDE)
#define MAT_ELEMS (NDIM * NDIM)
#define SCALE 144.269504088896340736f   // 100 * log2(e)
#define NITERS 21

__device__ __forceinline__ float ex2f(float x) {
    float y; asm("ex2.approx.ftz.f32 %0, %1;" : "=f"(y) : "f"(x)); return y;
}
__device__ __forceinline__ float lg2f(float x) {
    float y; asm("lg2.approx.ftz.f32 %0, %1;" : "=f"(y) : "f"(x)); return y;
}

__global__ __launch_bounds__(THREADS, 3)
void sinkhorn_kernel(const float* __restrict__ in, float* __restrict__ out)
{
    __shared__ float sy[NMAT_PER_BLOCK * MAT_SMEM];   // padded matrices (base-2 scaled)
    __shared__ __align__(16) float sU[NMAT_PER_BLOCK * NDIM];
    __shared__ __align__(16) float sV[NMAT_PER_BLOCK * NDIM];

    const int tid = threadIdx.x;
    const long long base = (long long)blockIdx.x * (NMAT_PER_BLOCK * MAT_ELEMS);

    // ---- load: coalesced float4 from global, scatter into padded smem, fused scale
    {
        const float4* in4 = (const float4*)(in + base);
        for (int k = tid; k < (NMAT_PER_BLOCK * MAT_ELEMS) / 4; k += THREADS) {
            float4 v = in4[k];
            float vals[4] = {v.x, v.y, v.z, v.w};
            int e = k * 4;
            #pragma unroll
            for (int q = 0; q < 4; q++) {
                int idx = e + q;
                int g   = idx / MAT_ELEMS;
                int rem = idx - g * MAT_ELEMS;
                int r   = rem / NDIM;
                int c   = rem - r * NDIM;
                sy[g * MAT_SMEM + r * STRIDE + c] = vals[q] * SCALE;
            }
        }
    }
    sV[tid] = 0.0f;                       // 288 == THREADS
    __syncthreads();

    const int g = tid / NDIM;          // which matrix in this block
    const int l = tid - g * NDIM;      // row index (row pass) / col index (col pass)

    const float4* U4 = (const float4*)&sU[g * NDIM];
    const float4* V4 = (const float4*)&sV[g * NDIM];
    float* U = &sU[g * NDIM];
    float* V = &sV[g * NDIM];
    const float* srow = &sy[g * MAT_SMEM + l * STRIDE];
    const float* scol = &sy[g * MAT_SMEM + l];

    #pragma unroll 1
    for (int it = 0; it < NITERS; it++) {
        // ---- row pass: U[l] = m + log2(sum_j 2^(srow[j] - V[j] - m))
        {
            float t[NDIM];
            float m0 = -1e30f, m1 = -1e30f, m2 = -1e30f, m3 = -1e30f;
            #pragma unroll
            for (int q = 0; q < 9; q++) {
                float4 v = V4[q];                 // broadcast across the group
                t[4*q+0] = srow[4*q+0] - v.x;
                t[4*q+1] = srow[4*q+1] - v.y;
                t[4*q+2] = srow[4*q+2] - v.z;
                t[4*q+3] = srow[4*q+3] - v.w;
                m0 = fmaxf(m0, t[4*q+0]);  m1 = fmaxf(m1, t[4*q+1]);
                m2 = fmaxf(m2, t[4*q+2]);  m3 = fmaxf(m3, t[4*q+3]);
            }
            float m = fmaxf(fmaxf(m0, m1), fmaxf(m2, m3));
            float s0 = 0.f, s1 = 0.f, s2 = 0.f, s3 = 0.f;
            #pragma unroll
            for (int j = 0; j < NDIM; j += 4) {
                s0 += ex2f(t[j]   - m);
                s1 += ex2f(t[j+1] - m);
                s2 += ex2f(t[j+2] - m);
                s3 += ex2f(t[j+3] - m);
            }
            U[l] = m + lg2f((s0 + s1) + (s2 + s3));
        }
        __syncthreads();

        // ---- col pass: V[l] = m + log2(sum_i 2^(scol[i*37] - U[i] - m))
        {
            float t[NDIM];
            float m0 = -1e30f, m1 = -1e30f, m2 = -1e30f, m3 = -1e30f;
            #pragma unroll
            for (int q = 0; q < 9; q++) {
                float4 u = U4[q];                 // broadcast across the group
                t[4*q+0] = scol[(4*q+0) * STRIDE] - u.x;
                t[4*q+1] = scol[(4*q+1) * STRIDE] - u.y;
                t[4*q+2] = scol[(4*q+2) * STRIDE] - u.z;
                t[4*q+3] = scol[(4*q+3) * STRIDE] - u.w;
                m0 = fmaxf(m0, t[4*q+0]);  m1 = fmaxf(m1, t[4*q+1]);
                m2 = fmaxf(m2, t[4*q+2]);  m3 = fmaxf(m3, t[4*q+3]);
            }
            float m = fmaxf(fmaxf(m0, m1), fmaxf(m2, m3));
            float s0 = 0.f, s1 = 0.f, s2 = 0.f, s3 = 0.f;
            #pragma unroll
            for (int i = 0; i < NDIM; i += 4) {
                s0 += ex2f(t[i]   - m);
                s1 += ex2f(t[i+1] - m);
                s2 += ex2f(t[i+2] - m);
                s3 += ex2f(t[i+3] - m);
            }
            V[l] = m + lg2f((s0 + s1) + (s2 + s3));
        }
        __syncthreads();
    }

    // ---- output: overwrite my row of sy with 2^(y - U - V), then float4 store
    {
        const float u = U[l];
        float* od = &sy[g * MAT_SMEM + l * STRIDE];
        #pragma unroll
        for (int q = 0; q < 9; q++) {
            float4 v = V4[q];
            float r0 = ex2f((od[4*q+0] - u) - v.x);
            float r1 = ex2f((od[4*q+1] - u) - v.y);
            float r2 = ex2f((od[4*q+2] - u) - v.z);
            float r3 = ex2f((od[4*q+3] - u) - v.w);
            od[4*q+0] = r0; od[4*q+1] = r1; od[4*q+2] = r2; od[4*q+3] = r3;
        }
    }
    __syncthreads();
    {
        float4* out4 = (float4*)(out + base);
        for (int k = tid; k < (NMAT_PER_BLOCK * MAT_ELEMS) / 4; k += THREADS) {
            int e = k * 4;
            float r[4];
            #pragma unroll
            for (int q = 0; q < 4; q++) {
                int idx = e + q;
                int gg  = idx / MAT_ELEMS;
                int rem = idx - gg * MAT_ELEMS;
                int rr  = rem / NDIM;
                int cc  = rem - rr * NDIM;
                r[q] = sy[gg * MAT_SMEM + rr * STRIDE + cc];
            }
            out4[k] = make_float4(r[0], r[1], r[2], r[3]);
        }
    }
}

extern "C" void kernel_launch(void* const* d_in, const int* in_sizes, int n_in,
                              void* d_out, int out_size) {
    const float* in = (const float*)d_in[0];
    float* out = (float*)d_out;
    int num_mats = in_sizes[0] / MAT_ELEMS;          // 65536
    int grid = num_mats / NMAT_PER_BLOCK;            // 8192
    sinkhorn_kernel<<<grid, THREADS>>>(in, out);
}